// round 8
// baseline (speedup 1.0000x reference)
#include <cuda_runtime.h>

// Problem constants (fixed by the reference setup)
#define DE   200          // entity / output dim
#define DR   200          // relation dim
#define DIN  400          // DE + DR
#define NB   4            // num bases
#define KTOT (NB * DIN)   // 1600 rows of the collapsed matvec

#define NBLK 148          // one wave
#define NTHR 512
#define NMM  37           // consumer (matvec) blocks: blockIdx 0..36
#define NSCAN (NBLK - NMM)   // 111 scan blocks
#define KCH  44           // k-rows per consumer block (37*44 = 1628 >= 1600)
#define KPG  22           // max k-rows per thread-group
#define CAP  2048         // match-slot capacity (expected ~8)

// persistent scratch (static device globals — no allocation). Everything is
// reset by the LAST block to finish, so each graph replay starts identical.
__device__ unsigned long long g_slot[CAP];  // 0 = empty; bit63|packed meta
__device__ int g_reserve;                   // slot allocator (true match count)
__device__ int g_scan_done;                 // scan-block completion count
__device__ int g_zero;                      // out[] zeroed flag
__device__ int g_done;                      // all-block completion (for reset)

__global__ void __launch_bounds__(NTHR, 1)
fused_kernel(const float* __restrict__ ent,
             const float* __restrict__ relemb,
             const float* __restrict__ basis,
             const float* __restrict__ att,
             const int*   __restrict__ node_id,
             const int*   __restrict__ edge_src,
             const int*   __restrict__ edge_dst,
             const int*   __restrict__ edge_type,
             const int*   __restrict__ rel_index,
             const int*   __restrict__ u_ptr,
             float* __restrict__ out,
             int E) {
    const int tid = threadIdx.x;
    __shared__ int s_last;

    if (blockIdx.x >= NMM) {
        // ───────────────────────── scan block ─────────────────────────
        // Publish = ONE 8-byte store carrying all meta (no fence, no flag).
        auto found = [&](int e) {
            int p = atomicAdd(&g_reserve, 1);
            if (p < CAP) {
                int s  = __ldcg(&edge_src[e]);     // these three issue together
                int ri = __ldcg(&rel_index[e]);
                int ty = __ldcg(&edge_type[e]);
                int nid = __ldcg(&node_id[s]);     // only serial dependency
                unsigned long long v = (1ULL << 63)
                    | ((unsigned long long)(unsigned)nid << 20)
                    | ((unsigned long long)(unsigned)ri  << 10)
                    | (unsigned long long)(unsigned)ty;
                *(volatile unsigned long long*)&g_slot[p] = v;
            }
        };
        const int sgt = (blockIdx.x - NMM) * NTHR + tid;
        const int SGT = NSCAN * NTHR;
        const int u   = *u_ptr;                 // L1-cached broadcast
        const int nv  = E >> 2;
        const int4* ed4 = (const int4*)edge_dst;
        for (int i = sgt; i < nv; i += 2 * SGT) {   // 2-wide MLP, 1 iter here
            int  i2 = i + SGT;
            bool h2 = i2 < nv;
            int4 v1 = __ldcg(&ed4[i]);
            int4 v2;
            if (h2) v2 = __ldcg(&ed4[i2]);
            int b1 = i << 2;
            if (v1.x == u) found(b1 + 0);
            if (v1.y == u) found(b1 + 1);
            if (v1.z == u) found(b1 + 2);
            if (v1.w == u) found(b1 + 3);
            if (h2) {
                int b2 = i2 << 2;
                if (v2.x == u) found(b2 + 0);
                if (v2.y == u) found(b2 + 1);
                if (v2.z == u) found(b2 + 2);
                if (v2.w == u) found(b2 + 3);
            }
        }
        for (int e = (nv << 2) + sgt; e < E; e += SGT) {   // scalar tail
            if (__ldcg(&edge_dst[e]) == u) found(e);
        }
        __syncthreads();
        if (tid == 0) { __threadfence(); atomicAdd(&g_scan_done, 1); }
    } else {
        // ──────────────────────── consumer block ────────────────────────
        const int k0   = blockIdx.x * KCH;
        const int kmax = (KTOT - k0) < KCH ? (KTOT - k0) : KCH;
        const int bs   = NTHR / kmax;           // slots per batch
        const bool act = tid < bs * kmax;
        const int mrel = tid / kmax;            // slot offset within batch
        const int kk   = tid - mrel * kmax;     // k-row within chunk

        __shared__ float sy[KCH];
        __shared__ float s1[256];
        __shared__ int   s_brk, s_cnt;

        // block 0 zeroes the REDG target, publishes g_zero
        if (blockIdx.x == 0) {
            if (tid < DE) out[tid] = 0.0f;
            __syncthreads();
            if (tid == 0) { __threadfence(); *(volatile int*)&g_zero = 1; }
        }
        int gz = *(volatile int*)&g_zero;       // early read (usually 1)

        // prefetch this block's basis chunk into registers (overlaps scan)
        const int g    = tid >> 8;
        const int o    = tid & 255;
        const int half = (kmax + 1) >> 1;
        float breg[KPG];
        if (o < DE) {
            #pragma unroll
            for (int j = 0; j < KPG; j++) {
                int kkk = g * half + j;
                breg[j] = (j < half && kkk < kmax)
                        ? __ldcg(&basis[(size_t)(k0 + kkk) * DE + o]) : 0.0f;
            }
        }
        if (tid < KCH) sy[tid] = 0.0f;
        __syncthreads();

        // streaming consume: each thread polls ITS slot directly and computes
        // the moment it is published (overlapped with the running scan).
        int processed = 0;
        for (;;) {
            if (act && processed + mrel < CAP) {
                const int mm = processed + mrel;
                unsigned long long v;
                for (;;) {
                    v = *(volatile unsigned long long*)&g_slot[mm];
                    if (v) break;
                    if (*(volatile int*)&g_scan_done == NSCAN) {
                        __threadfence();
                        if (*(volatile int*)&g_reserve <= mm) break;  // v==0
                    }
                }
                if (v) {
                    int nid = (int)((v >> 20) & 0x1FFFF);
                    int ri  = (int)((v >> 10) & 0x3FF);
                    int ty  = (int)(v & 0x3FF);
                    int k = k0 + kk;
                    int b = k / DIN;
                    int i = k - b * DIN;
                    float x = (i < DE)
                        ? __ldcg(&ent[(size_t)nid * DE + i])
                        : __ldcg(&relemb[(size_t)ri * DR + (i - DE)]);
                    float a = att[ty * NB + b];   // parallel with x load
                    atomicAdd(&sy[kk], a * x);
                }
            }
            processed += bs;
            __syncthreads();
            if (tid == 0) {
                int brk = 0;
                if (*(volatile int*)&g_scan_done == NSCAN) {
                    __threadfence();
                    int r = *(volatile int*)&g_reserve;
                    if (r <= processed || processed >= CAP) { brk = 1; s_cnt = r; }
                }
                s_brk = brk;
            }
            __syncthreads();
            if (s_brk) break;
        }

        // combine halves in smem -> ONE REDG lane per output element
        const int   cnt = s_cnt;
        const float inv = 1.0f / fmaxf((float)cnt, 1.0f);
        float acc = 0.0f;
        if (o < DE) {
            #pragma unroll
            for (int j = 0; j < KPG; j++) {
                int kkk = g * half + j;
                if (j < half && kkk < kmax) acc += sy[kkk] * breg[j];
            }
            if (g == 1) s1[o] = acc;
        }
        __syncthreads();
        if (o < DE && g == 0) {
            if (!gz) { while (*(volatile int*)&g_zero == 0) { } }
            __threadfence();                      // acquire vs out-zeroing
            atomicAdd(&out[o], (acc + s1[o]) * inv);  // fire-and-forget REDG
        }
    }

    // ── Tail: last block to finish resets scratch (parallel, no spin) ──
    __syncthreads();
    if (tid == 0) {
        __threadfence();
        int a = atomicAdd(&g_done, 1);
        s_last = (a == NBLK - 1) ? 1 : 0;
    }
    __syncthreads();
    if (s_last) {
        int rc = *(volatile int*)&g_reserve;
        if (rc > CAP) rc = CAP;
        for (int m = tid; m < rc; m += NTHR) g_slot[m] = 0ULL;
        if (tid == 0) { g_reserve = 0; g_scan_done = 0; g_zero = 0; g_done = 0; }
    }
}

extern "C" void kernel_launch(void* const* d_in, const int* in_sizes, int n_in,
                              void* d_out, int out_size) {
    const float* ent    = (const float*)d_in[0];  // [100000, 200]
    const float* relemb = (const float*)d_in[1];  // [200, 200]
    const float* basis  = (const float*)d_in[2];  // [4, 400, 200]
    const float* att    = (const float*)d_in[3];  // [400, 4]
    const int* node_id  = (const int*)d_in[4];    // [50000]
    const int* edge_src = (const int*)d_in[5];    // [400000]
    const int* edge_dst = (const int*)d_in[6];    // [400000]
    const int* edge_typ = (const int*)d_in[7];    // [400000]
    const int* rel_idx  = (const int*)d_in[8];    // [400000]
    const int* u_ptr    = (const int*)d_in[9];    // scalar
    float* out = (float*)d_out;                   // [200]

    int E = in_sizes[6];

    fused_kernel<<<NBLK, NTHR>>>(ent, relemb, basis, att,
                                 node_id, edge_src, edge_dst, edge_typ, rel_idx,
                                 u_ptr, out, E);
}

// round 9
// speedup vs baseline: 1.1488x; 1.1488x over previous
#include <cuda_runtime.h>

// Problem constants (fixed by the reference setup)
#define DE   200          // entity / output dim
#define DR   200          // relation dim
#define DIN  400          // DE + DR
#define NB   4            // num bases
#define KTOT (NB * DIN)   // 1600 rows of the collapsed matvec

#define NBLK 148          // one wave
#define NTHR 512
#define NMM  37           // consumer (matvec) blocks: blockIdx 0..36
#define KCH  44           // k-rows per consumer block (37*44 = 1628 >= 1600)
#define KPG  22           // max k-rows per thread-group (2 groups x 256 thr)
#define MAXM 1024         // slot capacity (expected ~8 matches)

// persistent scratch (static device globals — no allocation).
// g_count is reset by the barrier releaser each launch; g_rel is monotonic;
// g_bar_count self-resets; slots are rewritten fresh before being read.
__device__ int                g_count;
__device__ unsigned           g_bar_count;
__device__ unsigned long long g_rel;          // low32 = seq, high32 = count
__device__ unsigned long long g_slot[MAXM];   // packed (nid<<20 | ri<<10 | ty)

__global__ void __launch_bounds__(NTHR, 1)
fused_kernel(const float* __restrict__ ent,
             const float* __restrict__ relemb,
             const float* __restrict__ basis,
             const float* __restrict__ att,
             const int*   __restrict__ node_id,
             const int*   __restrict__ edge_src,
             const int*   __restrict__ edge_dst,
             const int*   __restrict__ edge_type,
             const int*   __restrict__ rel_index,
             const int*   __restrict__ u_ptr,
             float* __restrict__ out,
             int E) {
    const int tid = threadIdx.x;
    const bool is_mv = (blockIdx.x < NMM);

    __shared__ float sy[KCH];
    __shared__ float s1[256];
    __shared__ unsigned long long s_rel;

    // Early: capture the current release sequence (stable until this launch's
    // own release) — overlapped with everything below.
    unsigned seq_old = 0;
    if (tid == 0) s_rel = *(volatile unsigned long long*)&g_rel;

    // block 0 zeroes the REDG target pre-barrier (barrier orders it
    // before every consumer's post-release REDG).
    if (blockIdx.x == 0 && tid < DE) out[tid] = 0.0f;

    // Consumer blocks prefetch their basis chunk into registers
    // (independent of the scan -> overlaps its latency).
    const int k0   = blockIdx.x * KCH;
    const int kmax = is_mv ? ((KTOT - k0) < KCH ? (KTOT - k0) : KCH) : 0;
    const int g    = tid >> 8;       // 0 or 1
    const int o    = tid & 255;      // output index within group
    float breg[KPG];
    if (is_mv && o < DE) {
        #pragma unroll
        for (int j = 0; j < KPG; j++) {
            int kk = g * KPG + j;
            breg[j] = (kk < kmax) ? __ldcg(&basis[(size_t)(k0 + kk) * DE + o]) : 0.0f;
        }
    }
    if (tid < KCH) sy[tid] = 0.0f;

    // ── Phase 1: scan edge_dst; finder resolves the pointer chain and
    //    publishes ONE packed 64-bit word per match. ──
    auto found = [&](int e) {
        int p = atomicAdd(&g_count, 1);
        if (p < MAXM) {
            int s  = __ldcg(&edge_src[e]);   // these three issue in parallel
            int ri = __ldcg(&rel_index[e]);
            int ty = __ldcg(&edge_type[e]);
            int nid = __ldcg(&node_id[s]);   // the only serial dependency
            g_slot[p] = ((unsigned long long)(unsigned)nid << 20)
                      | ((unsigned long long)(unsigned)ri  << 10)
                      |  (unsigned long long)(unsigned)ty;
        }
    };
    {
        const int u  = *u_ptr;               // L1-cached broadcast
        const int gt = blockIdx.x * NTHR + tid;
        const int GT = NBLK * NTHR;
        const int nv = E >> 2;
        const int4* ed4 = (const int4*)edge_dst;
        for (int i = gt; i < nv; i += 2 * GT) {       // 2-wide MLP
            int  i2 = i + GT;
            bool h2 = i2 < nv;
            int4 v1 = __ldcg(&ed4[i]);
            int4 v2;
            if (h2) v2 = __ldcg(&ed4[i2]);
            int b1 = i << 2;
            if (v1.x == u) found(b1 + 0);
            if (v1.y == u) found(b1 + 1);
            if (v1.z == u) found(b1 + 2);
            if (v1.w == u) found(b1 + 3);
            if (h2) {
                int b2 = i2 << 2;
                if (v2.x == u) found(b2 + 0);
                if (v2.y == u) found(b2 + 1);
                if (v2.z == u) found(b2 + 2);
                if (v2.w == u) found(b2 + 3);
            }
        }
        for (int e = (nv << 2) + gt; e < E; e += GT) {  // scalar tail
            if (__ldcg(&edge_dst[e]) == u) found(e);
        }
    }

    // ── Barrier arrival. The LAST arriver packs the match count into the
    //    release word (so consumers never load g_count) and resets it.
    //    Scan-only blocks exit immediately after arriving. ──
    __syncthreads();                          // also makes s_rel visible
    seq_old = (unsigned)s_rel;
    if (tid == 0) {
        __threadfence();                      // publish this block's stores
        unsigned a = atomicAdd(&g_bar_count, 1u);
        if (a == NBLK - 1) {                  // releaser
            int cnt = g_count;
            g_count = 0;                      // fold reset into the barrier
            g_bar_count = 0;
            __threadfence();
            atomicExch(&g_rel, ((unsigned long long)(unsigned)cnt << 32)
                               | (unsigned long long)(seq_old + 1u));
        }
    }

    if (!is_mv) return;                       // scan-only blocks are done

    // ── Consumers wait for release (tid0 spins, smem-broadcast) ──
    if (tid == 0) {
        unsigned long long v;
        do { v = *(volatile unsigned long long*)&g_rel; }
        while ((unsigned)v == seq_old);
        __threadfence();                      // acquire
        s_rel = v;
    }
    __syncthreads();
    const int   cnt  = (int)(s_rel >> 32);
    const int   cntc = cnt < MAXM ? cnt : MAXM;
    const float inv  = 1.0f / fmaxf((float)cnt, 1.0f);

    // ── Phase 2: y[kk] = sum_m att[m][b] * xj_m[i] for this block's k-rows ──
    if (cntc > 0) {
        const int total = cntc * kmax;
        for (int p = tid; p < total; p += NTHR) {
            int mm = p / kmax;
            int kk = p - mm * kmax;
            unsigned long long v = g_slot[mm];       // ONE meta load
            int nid = (int)((v >> 20) & 0x1FFFF);
            int ri  = (int)((v >> 10) & 0x3FF);
            int ty  = (int)(v & 0x3FF);
            int k = k0 + kk;
            int b = k / DIN;
            int i = k - b * DIN;
            float x = (i < DE)
                ? __ldcg(&ent[(size_t)nid * DE + i])
                : __ldcg(&relemb[(size_t)ri * DR + (i - DE)]);
            float a = att[ty * NB + b];              // parallel with x load
            atomicAdd(&sy[kk], a * x);
        }
    }
    __syncthreads();

    // combine halves in smem -> ONE REDG lane per output element, pre-scaled
    float acc = 0.0f;
    if (o < DE) {
        #pragma unroll
        for (int j = 0; j < KPG; j++) {
            int kk = g * KPG + j;
            if (kk < kmax) acc += sy[kk] * breg[j];
        }
        if (g == 1) s1[o] = acc;
    }
    __syncthreads();
    if (o < DE && g == 0 && cntc > 0) {
        atomicAdd(&out[o], (acc + s1[o]) * inv);     // fire-and-forget REDG
    }
    // no reset tail: count reset at barrier, slots rewritten next launch,
    // g_rel monotonic, g_bar_count self-reset.
}

extern "C" void kernel_launch(void* const* d_in, const int* in_sizes, int n_in,
                              void* d_out, int out_size) {
    const float* ent    = (const float*)d_in[0];  // [100000, 200]
    const float* relemb = (const float*)d_in[1];  // [200, 200]
    const float* basis  = (const float*)d_in[2];  // [4, 400, 200]
    const float* att    = (const float*)d_in[3];  // [400, 4]
    const int* node_id  = (const int*)d_in[4];    // [50000]
    const int* edge_src = (const int*)d_in[5];    // [400000]
    const int* edge_dst = (const int*)d_in[6];    // [400000]
    const int* edge_typ = (const int*)d_in[7];    // [400000]
    const int* rel_idx  = (const int*)d_in[8];    // [400000]
    const int* u_ptr    = (const int*)d_in[9];    // scalar
    float* out = (float*)d_out;                   // [200]

    int E = in_sizes[6];

    fused_kernel<<<NBLK, NTHR>>>(ent, relemb, basis, att,
                                 node_id, edge_src, edge_dst, edge_typ, rel_idx,
                                 u_ptr, out, E);
}